// round 8
// baseline (speedup 1.0000x reference)
#include <cuda_runtime.h>
#include <math.h>

#define PI_F 3.14159265358979323846f

__device__ float g_coef[256 * 6];

__global__ void prep_kernel(const float* __restrict__ theta, int B,
                            float sW, float sH) {
    int i = blockIdx.x * blockDim.x + threadIdx.x;
    if (i >= B * 6) return;
    int rc = i % 6;
    int r = rc / 3;
    const float m1[6] = {1.0f,  PI_F,        0.2f,  PI_F,        1.0f, 0.2f};
    const float m2[6] = {0.5f, -PI_F * 0.5f, -0.1f, -PI_F * 0.5f, 0.5f, -0.1f};
    float v = fmaf(theta[i], m1[rc], m2[rc]);
    g_coef[i] = v * (r == 0 ? sW : sH);
}

struct Coef { float c0, c1, c2, c3, c4, c5, Wm1, Hm1, inv; };

// Process one 4x2 output rect at (wpix, hpix). Identical arithmetic to the
// reference per-pixel path (classification + bilinear).
__device__ __forceinline__ void do_rect(
    const Coef& k, const float* __restrict__ imgb, float* __restrict__ op0,
    int W, int wpix, int hpix)
{
    const float fw = (float)wpix;
    const float xnA = fw * k.inv;
    const float xnB = (fw + 3.0f) * k.inv;

    float bxr[2], byr[2];
#pragma unroll
    for (int r = 0; r < 2; r++) {
        const float yn = (float)(hpix + r) * k.inv;
        bxr[r] = fmaf(k.c1, yn, k.c2);
        byr[r] = fmaf(k.c4, yn, k.c5);
    }

    bool allin = true, outL = true, outR = true, outT = true, outBo = true;
#pragma unroll
    for (int r = 0; r < 2; r++) {
        const float xA = fmaf(k.c0, xnA, bxr[r]), xB = fmaf(k.c0, xnB, bxr[r]);
        const float yA = fmaf(k.c3, xnA, byr[r]), yB = fmaf(k.c3, xnB, byr[r]);
        allin &= (xA >= 0.0f) & (xB >= 0.0f) & (xA < k.Wm1) & (xB < k.Wm1) &
                 (yA >= 0.0f) & (yB >= 0.0f) & (yA < k.Hm1) & (yB < k.Hm1);
        outL &= (xA < 0.0f) & (xB < 0.0f);
        outR &= (xA >= k.Wm1) & (xB >= k.Wm1);
        outT &= (yA < 0.0f) & (yB < 0.0f);
        outBo &= (yA >= k.Hm1) & (yB >= k.Hm1);
    }

    if (outL | outR | outT | outBo) {
        const float4 z = make_float4(0.f, 0.f, 0.f, 0.f);
        __stcs(reinterpret_cast<float4*>(op0), z);
        __stcs(reinterpret_cast<float4*>(op0 + W), z);
        return;
    }

    if (allin) {
#pragma unroll
        for (int r = 0; r < 2; r++) {
            const float bx = bxr[r], by = byr[r];
            int   idx[4];
            float wx0[4], wx1[4], wy0[4], wy1[4];
#pragma unroll
            for (int i = 0; i < 4; i++) {
                const float xn = (fw + (float)i) * k.inv;
                const float xs = fmaf(k.c0, xn, bx);
                const float ys = fmaf(k.c3, xn, by);
                const int x0 = (int)xs;
                const int y0 = (int)ys;
                const float x0f = (float)x0;
                const float y0f = (float)y0;
                wx0[i] = xs - x0f;
                wx1[i] = (x0f + 1.0f) - xs;
                wy0[i] = ys - y0f;
                wy1[i] = (y0f + 1.0f) - ys;
                idx[i] = y0 * W + x0;
            }
            float Ia[4], Ib[4], Ic[4], Id[4];
#pragma unroll
            for (int i = 0; i < 4; i++) {
                Ia[i] = __ldg(imgb + idx[i]);
                Ic[i] = __ldg(imgb + idx[i] + 1);
                Ib[i] = __ldg(imgb + idx[i] + W);
                Id[i] = __ldg(imgb + idx[i] + W + 1);
            }
            float4 res;
            float* rp = &res.x;
#pragma unroll
            for (int i = 0; i < 4; i++) {
                rp[i] = wy1[i] * fmaf(wx1[i], Ia[i], wx0[i] * Ic[i]) +
                        wy0[i] * fmaf(wx1[i], Ib[i], wx0[i] * Id[i]);
            }
            __stcs(reinterpret_cast<float4*>(op0 + r * W), res);
        }
        return;
    }

    // Mixed rect: per-pixel branch, identical predicate arithmetic.
#pragma unroll
    for (int r = 0; r < 2; r++) {
        const float bx = bxr[r], by = byr[r];
        float res[4];
#pragma unroll
        for (int p = 0; p < 4; p++) {
            const float xn = (fw + (float)p) * k.inv;
            const float xs = fmaf(k.c0, xn, bx);
            const float ys = fmaf(k.c3, xn, by);
            float v = 0.0f;
            if (xs >= 0.0f && xs < k.Wm1 && ys >= 0.0f && ys < k.Hm1) {
                const int x0 = (int)xs;
                const int y0 = (int)ys;
                const float x0f = (float)x0;
                const float y0f = (float)y0;
                const float fx0 = xs - x0f;
                const float fx1 = (x0f + 1.0f) - xs;
                const float fy0 = ys - y0f;
                const float fy1 = (y0f + 1.0f) - ys;
                const int idx = y0 * W + x0;
                const float Ia = __ldg(imgb + idx);
                const float Ic = __ldg(imgb + idx + 1);
                const float Ib = __ldg(imgb + idx + W);
                const float Id = __ldg(imgb + idx + W + 1);
                v = fy1 * fmaf(fx1, Ia, fx0 * Ic) +
                    fy0 * fmaf(fx1, Ib, fx0 * Id);
            }
            res[p] = v;
        }
        __stcs(reinterpret_cast<float4*>(op0 + r * W),
               make_float4(res[0], res[1], res[2], res[3]));
    }
}

// Block = 256 threads covering a 32x64 output tile; each thread owns a 4x2
// rect. Two intra-block layouts chosen per batch (uniform, no divergence):
//   WIDE: warp covers 32x8  (gathers spread along output x)
//   TALL: warp covers 8x32  (gathers spread along output y)
// TALL wins when |c3| > |c4| (input-row spread per LDG is then smaller).
__global__ __launch_bounds__(256)
void stn_kernel(const float* __restrict__ img, float* __restrict__ out,
                int H, int W, float inv) {
    const int b = blockIdx.z;

    Coef k;
    k.c0 = g_coef[b * 6 + 0];
    k.c1 = g_coef[b * 6 + 1];
    k.c2 = g_coef[b * 6 + 2];
    k.c3 = g_coef[b * 6 + 3];
    k.c4 = g_coef[b * 6 + 4];
    k.c5 = g_coef[b * 6 + 5];
    k.Wm1 = (float)(W - 1);
    k.Hm1 = (float)(H - 1);
    k.inv = inv;

    const int tx = threadIdx.x;          // 0..31
    const int ty = threadIdx.y;          // 0..7 (warp id)

    int wpix, hpix;
    if (fabsf(k.c3) > fabsf(k.c4)) {
        // TALL: warp = 8x * 32y. lanes: 2 x-groups * 16 y.
        const int lx = tx & 1;
        const int ly = tx >> 1;          // 0..15
        const int wx = ty & 3;           // 4 warps across x
        const int wy = ty >> 2;          // 2 warps down y
        wpix = blockIdx.x * 32 + wx * 8 + lx * 4;
        hpix = blockIdx.y * 64 + wy * 32 + ly * 2;
    } else {
        // WIDE: warp = 32x * 8y. lanes: 8 x-groups * 4 y.
        const int lx = tx & 7;
        const int ly = tx >> 3;          // 0..3
        wpix = blockIdx.x * 32 + lx * 4;
        hpix = blockIdx.y * 64 + ty * 8 + ly * 2;
    }
    if (hpix >= H || wpix >= W) return;

    const float* __restrict__ imgb = img + (size_t)b * H * W;
    float* __restrict__ op0 = out + (size_t)b * H * W + (size_t)hpix * W + wpix;

    do_rect(k, imgb, op0, W, wpix, hpix);
}

extern "C" void kernel_launch(void* const* d_in, const int* in_sizes, int n_in,
                              void* d_out, int out_size) {
    const float* img   = (const float*)d_in[0];
    const float* theta = (const float*)d_in[1];

    const int B = in_sizes[1] / 6;
    const long long hw = (long long)in_sizes[0] / B;
    const int W = (int)(sqrt((double)hw) + 0.5);
    const int H = (int)(hw / W);

    prep_kernel<<<(B * 6 + 127) / 128, 128>>>(theta, B, (float)(W - 1), (float)(H - 1));

    dim3 blk(32, 8, 1);
    dim3 grd((W + 31) / 32, (H + 63) / 64, B);
    stn_kernel<<<grd, blk>>>(img, (float*)d_out, H, W, 1.0f / (float)(W - 1));
}

// round 9
// speedup vs baseline: 1.1230x; 1.1230x over previous
#include <cuda_runtime.h>
#include <math.h>

#define PI_F 3.14159265358979323846f

__device__ float g_coef[256 * 6];

__global__ void prep_kernel(const float* __restrict__ theta, int B,
                            float sW, float sH) {
    int i = blockIdx.x * blockDim.x + threadIdx.x;
    if (i >= B * 6) return;
    int rc = i % 6;
    int r = rc / 3;
    const float m1[6] = {1.0f,  PI_F,        0.2f,  PI_F,        1.0f, 0.2f};
    const float m2[6] = {0.5f, -PI_F * 0.5f, -0.1f, -PI_F * 0.5f, 0.5f, -0.1f};
    float v = fmaf(theta[i], m1[rc], m2[rc]);
    g_coef[i] = v * (r == 0 ? sW : sH);
}

// Block = 128 threads covering a 32x32 output tile. Warp covers 32x8
// (8 x-groups * 4 y-lanes); each thread owns a 4x2 pixel rectangle.
__global__ __launch_bounds__(128, 12)
void stn_kernel(const float* __restrict__ img, float* __restrict__ out,
                int H, int W, float inv) {
    const int b = blockIdx.z;
    const int tx = threadIdx.x;          // 0..31
    const int ty = threadIdx.y;          // 0..3 (warp id)
    const int lx = tx & 7;               // x-group within warp
    const int ly = tx >> 3;              // y-lane within warp (0..3)

    const int wpix = blockIdx.x * 32 + lx * 4;          // 4 x pixels
    const int hpix = blockIdx.y * 32 + ty * 8 + ly * 2; // 2 y rows
    if (hpix >= H || wpix >= W) return;

    const float c0 = g_coef[b * 6 + 0];
    const float c1 = g_coef[b * 6 + 1];
    const float c2 = g_coef[b * 6 + 2];
    const float c3 = g_coef[b * 6 + 3];
    const float c4 = g_coef[b * 6 + 4];
    const float c5 = g_coef[b * 6 + 5];

    const float Wm1 = (float)(W - 1);
    const float Hm1 = (float)(H - 1);
    const float fw = (float)wpix;
    const float xnA = fw * inv;
    const float xnB = (fw + 3.0f) * inv;

    // Per-row bases (exact same arithmetic as the per-pixel reference path).
    float bxr[2], byr[2];
#pragma unroll
    for (int r = 0; r < 2; r++) {
        const float yn = (float)(hpix + r) * inv;
        bxr[r] = fmaf(c1, yn, c2);
        byr[r] = fmaf(c4, yn, c5);
    }

    // Rectangle classification via the 4 corners (xs/ys linear in w and h).
    bool allin = true, outL = true, outR = true, outT = true, outBo = true;
#pragma unroll
    for (int r = 0; r < 2; r++) {
        const float xA = fmaf(c0, xnA, bxr[r]), xB = fmaf(c0, xnB, bxr[r]);
        const float yA = fmaf(c3, xnA, byr[r]), yB = fmaf(c3, xnB, byr[r]);
        allin &= (xA >= 0.0f) & (xB >= 0.0f) & (xA < Wm1) & (xB < Wm1) &
                 (yA >= 0.0f) & (yB >= 0.0f) & (yA < Hm1) & (yB < Hm1);
        outL &= (xA < 0.0f) & (xB < 0.0f);
        outR &= (xA >= Wm1) & (xB >= Wm1);
        outT &= (yA < 0.0f) & (yB < 0.0f);
        outBo &= (yA >= Hm1) & (yB >= Hm1);
    }
    const bool allout = outL | outR | outT | outBo;

    const float* __restrict__ imgb = img + (size_t)b * H * W;
    float* __restrict__ op0 = out + (size_t)b * H * W + (size_t)hpix * W + wpix;

    if (allout) {
        const float4 z = make_float4(0.f, 0.f, 0.f, 0.f);
        __stcs(reinterpret_cast<float4*>(op0), z);
        __stcs(reinterpret_cast<float4*>(op0 + W), z);
        return;
    }

    if (allin) {
#pragma unroll
        for (int r = 0; r < 2; r++) {
            const float bx = bxr[r], by = byr[r];
            int   idx[4];
            float wx0[4], wx1[4], wy0[4], wy1[4];
#pragma unroll
            for (int i = 0; i < 4; i++) {
                const float xn = (fw + (float)i) * inv;
                const float xs = fmaf(c0, xn, bx);
                const float ys = fmaf(c3, xn, by);
                const int x0 = (int)xs;          // xs >= 0 guaranteed
                const int y0 = (int)ys;
                const float x0f = (float)x0;
                const float y0f = (float)y0;
                wx0[i] = xs - x0f;
                wx1[i] = (x0f + 1.0f) - xs;
                wy0[i] = ys - y0f;
                wy1[i] = (y0f + 1.0f) - ys;
                idx[i] = y0 * W + x0;
            }
            float Ia[4], Ib[4], Ic[4], Id[4];
#pragma unroll
            for (int i = 0; i < 4; i++) {
                Ia[i] = __ldg(imgb + idx[i]);
                Ic[i] = __ldg(imgb + idx[i] + 1);
                Ib[i] = __ldg(imgb + idx[i] + W);
                Id[i] = __ldg(imgb + idx[i] + W + 1);
            }
            float4 res;
            float* rp = &res.x;
#pragma unroll
            for (int i = 0; i < 4; i++) {
                rp[i] = wy1[i] * fmaf(wx1[i], Ia[i], wx0[i] * Ic[i]) +
                        wy0[i] * fmaf(wx1[i], Ib[i], wx0[i] * Id[i]);
            }
            __stcs(reinterpret_cast<float4*>(op0 + r * W), res);
        }
        return;
    }

    // Mixed rectangle: per-pixel branch, identical predicate arithmetic.
#pragma unroll
    for (int r = 0; r < 2; r++) {
        const float bx = bxr[r], by = byr[r];
        float res[4];
#pragma unroll
        for (int p = 0; p < 4; p++) {
            const float xn = (fw + (float)p) * inv;
            const float xs = fmaf(c0, xn, bx);
            const float ys = fmaf(c3, xn, by);
            float v = 0.0f;
            if (xs >= 0.0f && xs < Wm1 && ys >= 0.0f && ys < Hm1) {
                const int x0 = (int)xs;
                const int y0 = (int)ys;
                const float x0f = (float)x0;
                const float y0f = (float)y0;
                const float fx0 = xs - x0f;
                const float fx1 = (x0f + 1.0f) - xs;
                const float fy0 = ys - y0f;
                const float fy1 = (y0f + 1.0f) - ys;
                const int idx = y0 * W + x0;
                const float Ia = __ldg(imgb + idx);
                const float Ic = __ldg(imgb + idx + 1);
                const float Ib = __ldg(imgb + idx + W);
                const float Id = __ldg(imgb + idx + W + 1);
                v = fy1 * fmaf(fx1, Ia, fx0 * Ic) +
                    fy0 * fmaf(fx1, Ib, fx0 * Id);
            }
            res[p] = v;
        }
        __stcs(reinterpret_cast<float4*>(op0 + r * W),
               make_float4(res[0], res[1], res[2], res[3]));
    }
}

extern "C" void kernel_launch(void* const* d_in, const int* in_sizes, int n_in,
                              void* d_out, int out_size) {
    const float* img   = (const float*)d_in[0];
    const float* theta = (const float*)d_in[1];

    const int B = in_sizes[1] / 6;
    const long long hw = (long long)in_sizes[0] / B;
    const int W = (int)(sqrt((double)hw) + 0.5);
    const int H = (int)(hw / W);

    prep_kernel<<<(B * 6 + 127) / 128, 128>>>(theta, B, (float)(W - 1), (float)(H - 1));

    dim3 blk(32, 4, 1);
    dim3 grd((W + 31) / 32, (H + 31) / 32, B);
    stn_kernel<<<grd, blk>>>(img, (float*)d_out, H, W, 1.0f / (float)(W - 1));
}

// round 10
// speedup vs baseline: 1.1476x; 1.0219x over previous
#include <cuda_runtime.h>
#include <math.h>

#define PI_F 3.14159265358979323846f
#define MAGIC_F 12582912.0f          // 1.5 * 2^23
#define MAGIC_I 0x4B400000

__device__ float g_coef[256 * 6];

__global__ void prep_kernel(const float* __restrict__ theta, int B,
                            float sW, float sH) {
    int i = blockIdx.x * blockDim.x + threadIdx.x;
    if (i >= B * 6) return;
    int rc = i % 6;
    int r = rc / 3;
    const float m1[6] = {1.0f,  PI_F,        0.2f,  PI_F,        1.0f, 0.2f};
    const float m2[6] = {0.5f, -PI_F * 0.5f, -0.1f, -PI_F * 0.5f, 0.5f, -0.1f};
    float v = fmaf(theta[i], m1[rc], m2[rc]);
    g_coef[i] = v * (r == 0 ? sW : sH);
}

// Block = 128 threads covering a 32x32 output tile. Warp covers 32x8
// (8 x-groups * 4 y-lanes); each thread owns a 4x2 pixel rectangle.
__global__ __launch_bounds__(128, 12)
void stn_kernel(const float* __restrict__ img, float* __restrict__ out,
                int H, int W, float inv) {
    const int b = blockIdx.z;
    const int tx = threadIdx.x;
    const int ty = threadIdx.y;
    const int lx = tx & 7;
    const int ly = tx >> 3;

    const int wpix = blockIdx.x * 32 + lx * 4;
    const int hpix = blockIdx.y * 32 + ty * 8 + ly * 2;
    if (hpix >= H || wpix >= W) return;

    const float c0 = g_coef[b * 6 + 0];
    const float c1 = g_coef[b * 6 + 1];
    const float c2 = g_coef[b * 6 + 2];
    const float c3 = g_coef[b * 6 + 3];
    const float c4 = g_coef[b * 6 + 4];
    const float c5 = g_coef[b * 6 + 5];

    const float Wm1 = (float)(W - 1);
    const float Hm1 = (float)(H - 1);
    const float fW  = (float)W;
    const float fw  = (float)wpix;
    const float xnA = fw * inv;
    const float xnB = (fw + 3.0f) * inv;

    float bxr[2], byr[2];
#pragma unroll
    for (int r = 0; r < 2; r++) {
        const float yn = (float)(hpix + r) * inv;
        bxr[r] = fmaf(c1, yn, c2);
        byr[r] = fmaf(c4, yn, c5);
    }

    // Classify the 4x2 rect via its 4 corners (xs/ys linear in w,h).
    bool allin = true, outL = true, outR = true, outT = true, outBo = true;
#pragma unroll
    for (int r = 0; r < 2; r++) {
        const float xA = fmaf(c0, xnA, bxr[r]), xB = fmaf(c0, xnB, bxr[r]);
        const float yA = fmaf(c3, xnA, byr[r]), yB = fmaf(c3, xnB, byr[r]);
        allin &= (xA >= 0.0f) & (xB >= 0.0f) & (xA < Wm1) & (xB < Wm1) &
                 (yA >= 0.0f) & (yB >= 0.0f) & (yA < Hm1) & (yB < Hm1);
        outL &= (xA < 0.0f) & (xB < 0.0f);
        outR &= (xA >= Wm1) & (xB >= Wm1);
        outT &= (yA < 0.0f) & (yB < 0.0f);
        outBo &= (yA >= Hm1) & (yB >= Hm1);
    }
    const bool allout = outL | outR | outT | outBo;

    const float* __restrict__ imgb = img + (size_t)b * H * W;
    float* __restrict__ op0 = out + (size_t)b * H * W + (size_t)hpix * W + wpix;

    if (allout) {
        const float4 z = make_float4(0.f, 0.f, 0.f, 0.f);
        __stcs(reinterpret_cast<float4*>(op0), z);
        __stcs(reinterpret_cast<float4*>(op0 + W), z);
        return;
    }

    if (allin) {
#pragma unroll
        for (int r = 0; r < 2; r++) {
            const float bx = bxr[r], by = byr[r];
            int   idx[4];
            float wx0[4], wx1[4], wy0[4], wy1[4];
#pragma unroll
            for (int i = 0; i < 4; i++) {
                const float xn = (fw + (float)i) * inv;
                const float xs = fmaf(c0, xn, bx);
                const float ys = fmaf(c3, xn, by);
                // Magic-number floor: x0f = RNE(xs-0.5) == floor(xs)
                // (xs-0.5 exact for xs in [0,2048); exact-integer xs may give
                //  floor-1 with wx=1/0 -> identical bilinear result, no OOB).
                const float x0f = ((xs - 0.5f) + MAGIC_F) - MAGIC_F;
                const float y0f = ((ys - 0.5f) + MAGIC_F) - MAGIC_F;
                wx0[i] = xs - x0f;
                wx1[i] = 1.0f - wx0[i];
                wy0[i] = ys - y0f;
                wy1[i] = 1.0f - wy0[i];
                // Flat index in fp (exact: idx < 2^22), extract via bits.
                const float fidx = fmaf(y0f, fW, x0f);
                idx[i] = __float_as_int(fidx + MAGIC_F) - MAGIC_I;
            }
            float Ia[4], Ib[4], Ic[4], Id[4];
#pragma unroll
            for (int i = 0; i < 4; i++) {
                Ia[i] = __ldg(imgb + idx[i]);
                Ic[i] = __ldg(imgb + idx[i] + 1);
                Ib[i] = __ldg(imgb + idx[i] + W);
                Id[i] = __ldg(imgb + idx[i] + W + 1);
            }
            float4 res;
            float* rp = &res.x;
#pragma unroll
            for (int i = 0; i < 4; i++) {
                rp[i] = wy1[i] * fmaf(wx1[i], Ia[i], wx0[i] * Ic[i]) +
                        wy0[i] * fmaf(wx1[i], Ib[i], wx0[i] * Id[i]);
            }
            __stcs(reinterpret_cast<float4*>(op0 + r * W), res);
        }
        return;
    }

    // Mixed rectangle: per-pixel branch (rare), reference-style arithmetic.
#pragma unroll
    for (int r = 0; r < 2; r++) {
        const float bx = bxr[r], by = byr[r];
        float res[4];
#pragma unroll
        for (int p = 0; p < 4; p++) {
            const float xn = (fw + (float)p) * inv;
            const float xs = fmaf(c0, xn, bx);
            const float ys = fmaf(c3, xn, by);
            float v = 0.0f;
            if (xs >= 0.0f && xs < Wm1 && ys >= 0.0f && ys < Hm1) {
                const int x0 = (int)xs;
                const int y0 = (int)ys;
                const float x0f = (float)x0;
                const float y0f = (float)y0;
                const float fx0 = xs - x0f;
                const float fx1 = (x0f + 1.0f) - xs;
                const float fy0 = ys - y0f;
                const float fy1 = (y0f + 1.0f) - ys;
                const int idx = y0 * W + x0;
                const float Ia = __ldg(imgb + idx);
                const float Ic = __ldg(imgb + idx + 1);
                const float Ib = __ldg(imgb + idx + W);
                const float Id = __ldg(imgb + idx + W + 1);
                v = fy1 * fmaf(fx1, Ia, fx0 * Ic) +
                    fy0 * fmaf(fx1, Ib, fx0 * Id);
            }
            res[p] = v;
        }
        __stcs(reinterpret_cast<float4*>(op0 + r * W),
               make_float4(res[0], res[1], res[2], res[3]));
    }
}

extern "C" void kernel_launch(void* const* d_in, const int* in_sizes, int n_in,
                              void* d_out, int out_size) {
    const float* img   = (const float*)d_in[0];
    const float* theta = (const float*)d_in[1];

    const int B = in_sizes[1] / 6;
    const long long hw = (long long)in_sizes[0] / B;
    const int W = (int)(sqrt((double)hw) + 0.5);
    const int H = (int)(hw / W);

    prep_kernel<<<(B * 6 + 127) / 128, 128>>>(theta, B, (float)(W - 1), (float)(H - 1));

    dim3 blk(32, 4, 1);
    dim3 grd((W + 31) / 32, (H + 31) / 32, B);
    stn_kernel<<<grd, blk>>>(img, (float*)d_out, H, W, 1.0f / (float)(W - 1));
}